// round 3
// baseline (speedup 1.0000x reference)
#include <cuda_runtime.h>
#include <cuda_bf16.h>
#include <cstddef>

// Problem constants (ResidualBlock: N=50000, K=16, DIM=256, LeakyReLU slope 0.2)
#define PN    50000
#define PK    16
#define PDIM  256
#define SLOPE 0.2f

// ---------------------------------------------------------------------------
// Scratch (no allocations allowed -> __device__ globals)
// ---------------------------------------------------------------------------
__device__ float g_a0[(size_t)PN * 64];    // init MLP output      [N, 64]
__device__ float g_a1[(size_t)PN * 128];   // LFA1 output          [N, 128]
__device__ float g_a2[(size_t)PN * 256];   // LFA2 output          [N, 256]

// ---------------------------------------------------------------------------
// GEMM: C[M,Ncols] = leaky(A[M,Kd] @ W[Kd,Ncols] + bias)  (+ optional res add)
// BM=64, BN=64, BK=16, 256 threads, 4x4 register tile per thread.
// ---------------------------------------------------------------------------
#define BM 64
#define BN 64
#define BK 16

__global__ __launch_bounds__(256) void gemm_leaky(
    const float* __restrict__ A, const float* __restrict__ W,
    const float* __restrict__ bias, const float* __restrict__ res,
    float* __restrict__ C, int M, int Kd, int Ncols)
{
    __shared__ float As[BK][BM + 1];   // +1 pad: conflict-free transposed stores
    __shared__ float Bs[BK][BN];

    const int tid  = threadIdx.x;
    const int tx   = tid & 15;         // col group (0..15) -> 4 cols each
    const int ty   = tid >> 4;         // row group (0..15) -> 4 rows each
    const int row0 = blockIdx.x * BM;
    const int col0 = blockIdx.y * BN;

    // A-tile loader: thread loads float4 of row (tid>>2), k-offset (tid&3)*4
    const int lr = tid >> 2;
    const int lk = (tid & 3) << 2;
    // B-tile loader: thread loads float4 of k-row (tid>>4), col-offset (tid&15)*4
    const int bkk = tid >> 4;
    const int bcc = (tid & 15) << 2;

    const int  ar   = row0 + lr;
    const bool aval = (ar < M);
    const float* Aptr = A + (size_t)ar * Kd + lk;
    const float* Wptr = W + (size_t)bkk * Ncols + col0 + bcc;

    float acc[4][4];
#pragma unroll
    for (int i = 0; i < 4; i++)
#pragma unroll
        for (int j = 0; j < 4; j++) acc[i][j] = 0.0f;

    for (int k0 = 0; k0 < Kd; k0 += BK) {
        float4 av = aval ? *(const float4*)(Aptr + k0)
                         : make_float4(0.f, 0.f, 0.f, 0.f);
        float4 bv = *(const float4*)(Wptr + (size_t)k0 * Ncols);

        As[lk + 0][lr] = av.x;
        As[lk + 1][lr] = av.y;
        As[lk + 2][lr] = av.z;
        As[lk + 3][lr] = av.w;
        *(float4*)&Bs[bkk][bcc] = bv;
        __syncthreads();

#pragma unroll
        for (int kk = 0; kk < BK; kk++) {
            const float a0 = As[kk][ty * 4 + 0];
            const float a1 = As[kk][ty * 4 + 1];
            const float a2 = As[kk][ty * 4 + 2];
            const float a3 = As[kk][ty * 4 + 3];
            const float4 b = *(const float4*)&Bs[kk][tx * 4];
            acc[0][0] = fmaf(a0, b.x, acc[0][0]);
            acc[0][1] = fmaf(a0, b.y, acc[0][1]);
            acc[0][2] = fmaf(a0, b.z, acc[0][2]);
            acc[0][3] = fmaf(a0, b.w, acc[0][3]);
            acc[1][0] = fmaf(a1, b.x, acc[1][0]);
            acc[1][1] = fmaf(a1, b.y, acc[1][1]);
            acc[1][2] = fmaf(a1, b.z, acc[1][2]);
            acc[1][3] = fmaf(a1, b.w, acc[1][3]);
            acc[2][0] = fmaf(a2, b.x, acc[2][0]);
            acc[2][1] = fmaf(a2, b.y, acc[2][1]);
            acc[2][2] = fmaf(a2, b.z, acc[2][2]);
            acc[2][3] = fmaf(a2, b.w, acc[2][3]);
            acc[3][0] = fmaf(a3, b.x, acc[3][0]);
            acc[3][1] = fmaf(a3, b.y, acc[3][1]);
            acc[3][2] = fmaf(a3, b.z, acc[3][2]);
            acc[3][3] = fmaf(a3, b.w, acc[3][3]);
        }
        __syncthreads();
    }

    const float4 bb = *(const float4*)(bias + col0 + tx * 4);
#pragma unroll
    for (int i = 0; i < 4; i++) {
        const int r = row0 + ty * 4 + i;
        if (r >= M) break;  // rows per thread are consecutive -> break is safe
        float4 v;
        v.x = acc[i][0] + bb.x;
        v.y = acc[i][1] + bb.y;
        v.z = acc[i][2] + bb.z;
        v.w = acc[i][3] + bb.w;
        v.x = v.x >= 0.f ? v.x : SLOPE * v.x;
        v.y = v.y >= 0.f ? v.y : SLOPE * v.y;
        v.z = v.z >= 0.f ? v.z : SLOPE * v.z;
        v.w = v.w >= 0.f ? v.w : SLOPE * v.w;
        const size_t off = (size_t)r * Ncols + col0 + tx * 4;
        if (res) {
            const float4 rv = *(const float4*)(res + off);
            v.x += rv.x; v.y += rv.y; v.z += rv.z; v.w += rv.w;
        }
        *(float4*)(C + off) = v;
    }
}

// ---------------------------------------------------------------------------
// LFA: out[n] = [ mean_k leaky(geom[n,k,:4] @ wg + bg),  mean_k feat[idx[n,k]] ]
// One warp per point; lane handles D/32 feature dims.
// ---------------------------------------------------------------------------
template <int D>
__global__ __launch_bounds__(256) void lfa_kernel(
    const float* __restrict__ geom, const int* __restrict__ idx,
    const float* __restrict__ feat, float* __restrict__ out,
    const float* __restrict__ wg, const float* __restrict__ bg, int N)
{
    __shared__ float sw[4][D];
    __shared__ float sb[D];
    for (int i = threadIdx.x; i < 4 * D; i += blockDim.x) sw[i / D][i % D] = wg[i];
    for (int i = threadIdx.x; i < D; i += blockDim.x) sb[i] = bg[i];
    __syncthreads();

    constexpr int DPL = D / 32;
    const int warp = threadIdx.x >> 5;
    const int lane = threadIdx.x & 31;
    const int wpb  = blockDim.x >> 5;

    for (int n = blockIdx.x * wpb + warp; n < N; n += gridDim.x * wpb) {
        float accG[DPL], accF[DPL];
#pragma unroll
        for (int q = 0; q < DPL; q++) { accG[q] = 0.f; accF[q] = 0.f; }

        const float* gptr = geom + (size_t)n * (PK * 4);
        const int*   iptr = idx  + (size_t)n * PK;

#pragma unroll
        for (int k = 0; k < PK; k++) {
            const float4 g  = *(const float4*)(gptr + k * 4);  // uniform -> broadcast
            const int    rw = iptr[k];                          // uniform
            const float* frow = feat + (size_t)rw * D;
#pragma unroll
            for (int q = 0; q < DPL; q++) {
                const int d = lane + q * 32;
                float v = sb[d];
                v = fmaf(g.x, sw[0][d], v);
                v = fmaf(g.y, sw[1][d], v);
                v = fmaf(g.z, sw[2][d], v);
                v = fmaf(g.w, sw[3][d], v);
                v = v >= 0.f ? v : SLOPE * v;
                accG[q] += v;
                accF[q] += frow[d];    // coalesced 128B per q across the warp
            }
        }

        float* o = out + (size_t)n * (2 * D);
        const float inv = 1.0f / (float)PK;
#pragma unroll
        for (int q = 0; q < DPL; q++) {
            o[lane + q * 32]     = accG[q] * inv;
            o[D + lane + q * 32] = accF[q] * inv;
        }
    }
}

// ---------------------------------------------------------------------------
// Launch
// ---------------------------------------------------------------------------
extern "C" void kernel_launch(void* const* d_in, const int* in_sizes, int n_in,
                              void* d_out, int out_size)
{
    // metadata order (reference setup_inputs):
    const float* x      = (const float*)d_in[0];   // input_features [N,256]
    const float* geom   = (const float*)d_in[1];   // geom_features  [N,16,4]
    const int*   idx    = (const int*)  d_in[2];   // closest_indices[N,16]
    const float* w_res  = (const float*)d_in[3];   // [256,256]
    const float* b_res  = (const float*)d_in[4];   // [256]
    const float* w_init = (const float*)d_in[5];   // [256,64]
    const float* b_init = (const float*)d_in[6];   // [64]
    const float* w_g1   = (const float*)d_in[7];   // [4,64]
    const float* b_g1   = (const float*)d_in[8];   // [64]
    const float* w_g2   = (const float*)d_in[9];   // [4,128]
    const float* b_g2   = (const float*)d_in[10];  // [128]
    const float* w_fin  = (const float*)d_in[11];  // [256,256]
    const float* b_fin  = (const float*)d_in[12];  // [256]
    float* out = (float*)d_out;

    float *a0, *a1, *a2;
    cudaGetSymbolAddress((void**)&a0, g_a0);
    cudaGetSymbolAddress((void**)&a1, g_a1);
    cudaGetSymbolAddress((void**)&a2, g_a2);

    const int M = PN;
    const dim3 gRes((M + BM - 1) / BM, PDIM / BN);    // 782 x 4
    const dim3 gInit((M + BM - 1) / BM, 64 / BN);     // 782 x 1
    const dim3 gFin((M + BM - 1) / BM, PDIM / BN);    // 782 x 4
    const int  lfaBlocks = (M + 7) / 8;               // 8 warps/block

    // 1) residual -> d_out (covers every output element: un-poisons d_out)
    gemm_leaky<<<gRes, 256>>>(x, w_res, b_res, nullptr, out, M, PDIM, PDIM);
    // 2) a0 = leaky(x @ w_init + b)
    gemm_leaky<<<gInit, 256>>>(x, w_init, b_init, nullptr, a0, M, PDIM, 64);
    // 3) LFA1: a1 = [mean leaky(geom@w_g1+b), mean gather(a0)]
    lfa_kernel<64><<<lfaBlocks, 256>>>(geom, idx, a0, a1, w_g1, b_g1, M);
    // 4) LFA2: a2 = [mean leaky(geom@w_g2+b), mean gather(a1)]
    lfa_kernel<128><<<lfaBlocks, 256>>>(geom, idx, a1, a2, w_g2, b_g2, M);
    // 5) out = leaky(a2 @ w_fin + b) + residual(d_out)
    gemm_leaky<<<gFin, 256>>>(a2, w_fin, b_fin, out, out, M, PDIM, PDIM);
}